// round 7
// baseline (speedup 1.0000x reference)
#include <cuda_runtime.h>

#define NMAX 100000
#define CUTOFF2 0.81f
#define PREFAC 138.93544539709032f

// SWAR constants for 2 guarded fields of width 5 at offsets 0,5; values are
// 4-bit xy cell coords (16x16 grid over the box, cell = 0.625).
#define SW2_M15 0x1EFu   // 15 in each field
#define SW2_K16 0x210u   // 16 in each field (guard bits)
#define SW2_K2  0x042u   // 2 in each field
#define SW2_K11 0x16Bu   // 11 in each field

__device__ __align__(16) float4 g_posq[NMAX];
__device__ __align__(8)  float2 g_sigeps[NMAX];
__device__ __align__(16) unsigned char g_q8[NMAX + 32];
__device__ double g_accum;
__device__ unsigned g_done;

__global__ void pack_kernel(const float* __restrict__ coords,
                            const float* __restrict__ charges,
                            const float* __restrict__ sigma,
                            const float* __restrict__ eps,
                            int n) {
    int a = blockIdx.x * blockDim.x + threadIdx.x;
    if (a == 0) { g_accum = 0.0; g_done = 0u; }
    if (a < n) {
        float x = coords[3*a], y = coords[3*a+1], z = coords[3*a+2];
        g_posq[a]   = make_float4(x, y, z, charges[a]);
        g_sigeps[a] = make_float2(sigma[a], eps[a]);
        // Exact 16x16 xy cell assignment (double mul avoids boundary misrounding).
        int qx = min(15, max(0, (int)((double)x * 1.6)));
        int qy = min(15, max(0, (int)((double)y * 1.6)));
        g_q8[a] = (unsigned char)(qx | (qy << 4));
    }
}

// Expand packed 4+4 into two guarded width-5 fields (bits 0-4 and 5-9).
__device__ __forceinline__ unsigned expand8(unsigned a) {
    return (a & 15u) | ((a & 0xF0u) << 1);
}

// Conservative xy filter: pass iff min-image |cell diff| <= 2 in x AND y.
// |diff| = 3 implies dx >= 2*0.625 = 1.25 > 0.9, so rejects are provably invalid.
__device__ __forceinline__ bool swar_pass(unsigned ea, unsigned eb) {
    unsigned d = (ea | SW2_K16) - eb;         // (16 + ca - cb) per field, no borrows
    unsigned f = (d & SW2_M15) + SW2_K2;      // (dc mod 16) + 2
    unsigned g = (f & SW2_M15) + SW2_K11;     // ((dc+2) mod 16) + 11
    return (g & SW2_K16) == 0u;               // guard set iff ((dc+2) mod 16) > 4
}

// Exact energy path (identical math to the reference), run densely on survivors.
__device__ __forceinline__ float pair_full(int i, int j,
                                           float Lx, float Ly, float Lz,
                                           float iLx, float iLy, float iLz) {
    float4 ai = g_posq[i];
    float4 aj = g_posq[j];
    float dx = ai.x - aj.x;
    float dy = ai.y - aj.y;
    float dz = ai.z - aj.z;
    dx -= Lx * rintf(dx * iLx);
    dy -= Ly * rintf(dy * iLy);
    dz -= Lz * rintf(dz * iLz);
    float r2 = dx*dx + dy*dy + dz*dz;
    bool valid = (r2 < CUTOFF2) && ((i / 3) != (j / 3));
    if (!valid) return 0.0f;
    float inv_r = rsqrtf(r2);
    float e = PREFAC * ai.w * aj.w * inv_r;
    float2 si = g_sigeps[i];
    float2 sj = g_sigeps[j];
    float sig = 0.5f * (si.x + sj.x);
    float ep  = sqrtf(si.y * sj.y);
    float sr2 = sig * sig / r2;
    float sr6 = sr2 * sr2 * sr2;
    return e + 4.0f * ep * (sr6 * sr6 - sr6);
}

extern __shared__ unsigned char s_q[];

// Compaction step: warp-uniform stack push + dense flush at >=32. Max stack
// occupancy is 31 + 32 = 63 entries.
#define COMPACT_SLOT(PASS, I, J)                                              \
    {                                                                         \
        unsigned m = __ballot_sync(0xffffffffu, (PASS));                      \
        if (PASS) wbuf[cnt + __popc(m & lmask)] =                             \
            make_uint2((unsigned)(I), (unsigned)(J));                         \
        cnt += __popc(m);                                                     \
        if (cnt >= 32) {                                                      \
            cnt -= 32;                                                        \
            __syncwarp();                                                     \
            uint2 e = wbuf[cnt + lane];                                       \
            acc += pair_full((int)e.x, (int)e.y, Lx, Ly, Lz, iLx, iLy, iLz);  \
        }                                                                     \
    }

__global__ void __launch_bounds__(768, 2)
pair_kernel(const int4* __restrict__ p4, int n4, int npairs,
            const float* __restrict__ box, int natoms, int tchunks,
            float* __restrict__ out) {
    // Cooperative smem fill of the quantized table (uint4 chunks).
    {
        const uint4* src = (const uint4*)g_q8;
        uint4* dst = (uint4*)s_q;
        for (int t = threadIdx.x; t < tchunks; t += blockDim.x) dst[t] = src[t];
    }
    // Per-warp 63-entry survivor stacks live after the table.
    uint2* allbuf = (uint2*)(s_q + tchunks * 16);
    __syncthreads();

    const float Lx = box[0], Ly = box[4], Lz = box[8];
    const float iLx = 1.0f / Lx, iLy = 1.0f / Ly, iLz = 1.0f / Lz;

    int lane = threadIdx.x & 31;
    int wid  = threadIdx.x >> 5;
    uint2* wbuf = allbuf + wid * 63;
    unsigned lmask = (1u << lane) - 1u;

    int stride = gridDim.x * blockDim.x;
    int wbase  = blockIdx.x * blockDim.x + (threadIdx.x & ~31);

    float acc = 0.0f;
    int cnt = 0;   // warp-uniform survivor count (stack depth)

    for (int base = wbase; base < n4; base += stride * 2) {
        // ---- Phase 1: 2 batched stream loads ----
        int i0 = base + lane;
        int i1 = i0 + stride;
        bool r0 = i0 < n4, r1 = i1 < n4;
        int4 p0 = make_int4(0,0,0,0), p1 = p0;
        if (r0) p0 = __ldcs(&p4[i0]);
        if (r1) p1 = __ldcs(&p4[i1]);

        // ---- Phase 2: all 8 LDS gathers + 4 filter evals, no STS between ----
        unsigned qa0 = s_q[p0.x], qb0 = s_q[p0.y], qc0 = s_q[p0.z], qd0 = s_q[p0.w];
        unsigned qa1 = s_q[p1.x], qb1 = s_q[p1.y], qc1 = s_q[p1.z], qd1 = s_q[p1.w];

        bool s0a = r0 && swar_pass(expand8(qa0), expand8(qb0));
        bool s0b = r0 && swar_pass(expand8(qc0), expand8(qd0));
        bool s1a = r1 && swar_pass(expand8(qa1), expand8(qb1));
        bool s1b = r1 && swar_pass(expand8(qc1), expand8(qd1));

        // ---- Phase 3: compaction (touches only wbuf + dense survivor path) ----
        COMPACT_SLOT(s0a, p0.x, p0.y)
        COMPACT_SLOT(s0b, p0.z, p0.w)
        COMPACT_SLOT(s1a, p1.x, p1.y)
        COMPACT_SLOT(s1b, p1.z, p1.w)
    }
    // Drain remaining survivors (< 32).
    __syncwarp();
    if (lane < cnt) {
        uint2 e = wbuf[lane];
        acc += pair_full((int)e.x, (int)e.y, Lx, Ly, Lz, iLx, iLy, iLz);
    }
    // Defensive odd-pair tail (not hit for 16M pairs).
    if (blockIdx.x == 0 && threadIdx.x == 0 && (npairs & 1)) {
        const int* pp = (const int*)p4;
        acc += pair_full(pp[2*(npairs-1)], pp[2*(npairs-1)+1],
                         Lx, Ly, Lz, iLx, iLy, iLz);
    }

    // Deterministic warp + block reduction in double, one atomic per block.
    double dacc = (double)acc;
    #pragma unroll
    for (int o = 16; o > 0; o >>= 1)
        dacc += __shfl_down_sync(0xffffffffu, dacc, o);

    __shared__ double wsum[32];
    __shared__ bool s_last;
    if (lane == 0) wsum[wid] = dacc;
    __syncthreads();
    if (wid == 0) {
        int nw = blockDim.x >> 5;
        double v = (lane < nw) ? wsum[lane] : 0.0;
        #pragma unroll
        for (int o = 16; o > 0; o >>= 1)
            v += __shfl_down_sync(0xffffffffu, v, o);
        if (lane == 0) {
            atomicAdd(&g_accum, v);
            __threadfence();
            unsigned old = atomicAdd(&g_done, 1u);
            s_last = (old == gridDim.x - 1);
        }
    }
    __syncthreads();
    if (s_last && threadIdx.x == 0) {
        out[0] = (float)(*(volatile double*)&g_accum);
    }
}

extern "C" void kernel_launch(void* const* d_in, const int* in_sizes, int n_in,
                              void* d_out, int out_size) {
    const float* coords  = (const float*)d_in[0];
    const float* box     = (const float*)d_in[1];
    const float* charges = (const float*)d_in[2];
    const float* sigma   = (const float*)d_in[3];
    const float* eps     = (const float*)d_in[4];
    const int*   pairs   = (const int*)d_in[5];

    int n      = in_sizes[2];       // N atoms
    int npairs = in_sizes[5] / 2;   // pair count
    int n4     = npairs / 2;        // int4 loads (2 pairs each)

    int tchunks = (n + 15) / 16;                  // 16B chunks for the u8 table
    int smem_bytes = tchunks * 16 + 24 * 63 * 8;  // table + 24 warp stacks
    cudaFuncSetAttribute(pair_kernel,
                         cudaFuncAttributeMaxDynamicSharedMemorySize, smem_bytes);

    int nsm = 148;
    cudaDeviceGetAttribute(&nsm, cudaDevAttrMultiProcessorCount, 0);

    pack_kernel<<<(n + 255) / 256, 256>>>(coords, charges, sigma, eps, n);
    pair_kernel<<<2 * nsm, 768, smem_bytes>>>((const int4*)pairs, n4, npairs, box,
                                              n, tchunks, (float*)d_out);
}

// round 8
// speedup vs baseline: 1.6845x; 1.6845x over previous
#include <cuda_runtime.h>

#define NMAX 100000
#define CUTOFF2 0.81f
#define PREFAC 138.93544539709032f

// SWAR constants: 3 fields of width 7 at bit offsets 0,7,14; values are 5-bit
// cell coords (32^3 grid, cell = 0.3125). Bit 5/6 headroom gives the guard.
#define SW_M31 0x7CF9Fu   // 31 in each field
#define SW_K32 0x81020u   // 32 in each field (guard bits)
#define SW_K3  0x0C183u   // 3 in each field
#define SW_K25 0x64C99u   // 25 in each field

__device__ __align__(16) float4 g_posq[NMAX];
__device__ __align__(8)  float2 g_sigeps[NMAX];
__device__ __align__(16) unsigned short g_qpos[NMAX + 16];
__device__ double g_accum;
__device__ unsigned g_done;

// Fully-coalesced pack: stage xyz through smem so global reads/writes vectorize.
__global__ void __launch_bounds__(256)
pack_kernel(const float* __restrict__ coords,
            const float* __restrict__ charges,
            const float* __restrict__ sigma,
            const float* __restrict__ eps,
            int n) {
    __shared__ float sc[256 * 3];
    int base = blockIdx.x * 256;
    int n3 = n * 3;
    for (int t = threadIdx.x; t < 768; t += 256) {
        int g = base * 3 + t;
        sc[t] = (g < n3) ? coords[g] : 0.0f;
    }
    __syncthreads();
    int a = base + threadIdx.x;
    if (a == 0) { g_accum = 0.0; g_done = 0u; }
    if (a < n) {
        float x = sc[threadIdx.x*3], y = sc[threadIdx.x*3+1], z = sc[threadIdx.x*3+2];
        g_posq[a]   = make_float4(x, y, z, charges[a]);
        g_sigeps[a] = make_float2(sigma[a], eps[a]);
        // Exact 32^3 cell assignment (double mul avoids boundary misrounding).
        int qx = min(31, max(0, (int)((double)x * 3.2)));
        int qy = min(31, max(0, (int)((double)y * 3.2)));
        int qz = min(31, max(0, (int)((double)z * 3.2)));
        g_qpos[a] = (unsigned short)(qx | (qy << 5) | (qz << 10));
    }
}

// Expand packed 5+5+5 cell coords into guarded 7-bit fields at offsets 0,7,14.
__device__ __forceinline__ unsigned expand_q(unsigned q) {
    return (q & 0x1Fu) | ((q << 2) & 0x0F80u) | ((q << 4) & 0x7C000u);
}

// Conservative filter: pass iff min-image |cell diff| <= 3 in every dim.
// (r < 0.9 with cell 0.3125 implies |cell diff| <= 3, so rejects are provably invalid.)
__device__ __forceinline__ bool swar_pass(unsigned ea, unsigned eb) {
    unsigned d = (ea | SW_K32) - eb;          // (32 + ca - cb) per field, no borrows
    unsigned f = (d & SW_M31) + SW_K3;        // (dc mod 32) + 3
    unsigned g = (f & SW_M31) + SW_K25;       // ((dc+3) mod 32) + 25
    return (g & SW_K32) == 0u;                // guard set iff ((dc+3) mod 32) > 6
}

// Exact energy path (identical math to the reference), run densely on survivors.
__device__ __forceinline__ float pair_full(int i, int j,
                                           float Lx, float Ly, float Lz,
                                           float iLx, float iLy, float iLz) {
    float4 ai = g_posq[i];
    float4 aj = g_posq[j];
    float dx = ai.x - aj.x;
    float dy = ai.y - aj.y;
    float dz = ai.z - aj.z;
    dx -= Lx * rintf(dx * iLx);
    dy -= Ly * rintf(dy * iLy);
    dz -= Lz * rintf(dz * iLz);
    float r2 = dx*dx + dy*dy + dz*dz;
    bool valid = (r2 < CUTOFF2) && ((i / 3) != (j / 3));
    if (!valid) return 0.0f;
    float inv_r = rsqrtf(r2);
    float e = PREFAC * ai.w * aj.w * inv_r;
    float2 si = g_sigeps[i];
    float2 sj = g_sigeps[j];
    float sig = 0.5f * (si.x + sj.x);
    float ep  = sqrtf(si.y * sj.y);
    float sr2 = sig * sig / r2;
    float sr6 = sr2 * sr2 * sr2;
    return e + 4.0f * ep * (sr6 * sr6 - sr6);
}

extern __shared__ unsigned short s_q[];

// Compaction step: warp-uniform stack push + dense flush at >=32. Max stack
// occupancy is 31 + 32 = 63 entries (64 allocated).
#define COMPACT_SLOT(PASS, I, J)                                              \
    {                                                                         \
        unsigned m = __ballot_sync(0xffffffffu, (PASS));                      \
        if (PASS) wbuf[cnt + __popc(m & lmask)] =                             \
            make_uint2((unsigned)(I), (unsigned)(J));                         \
        cnt += __popc(m);                                                     \
        if (cnt >= 32) {                                                      \
            cnt -= 32;                                                        \
            __syncwarp();                                                     \
            uint2 e = wbuf[cnt + lane];                                       \
            acc += pair_full((int)e.x, (int)e.y, Lx, Ly, Lz, iLx, iLy, iLz);  \
        }                                                                     \
    }

__global__ void __launch_bounds__(1024, 1)
pair_kernel(const int4* __restrict__ p4, int n4, int npairs,
            const float* __restrict__ box, int natoms, int tchunks,
            float* __restrict__ out) {
    // Cooperative smem fill of the quantized table (uint4 chunks).
    {
        const uint4* src = (const uint4*)g_qpos;
        uint4* dst = (uint4*)s_q;
        for (int t = threadIdx.x; t < tchunks; t += blockDim.x) dst[t] = src[t];
    }
    // Per-warp survivor stacks live after the table.
    uint2* allbuf = (uint2*)(s_q + tchunks * 8);
    __syncthreads();

    const float Lx = box[0], Ly = box[4], Lz = box[8];
    const float iLx = 1.0f / Lx, iLy = 1.0f / Ly, iLz = 1.0f / Lz;

    int lane = threadIdx.x & 31;
    int wid  = threadIdx.x >> 5;
    uint2* wbuf = allbuf + wid * 64;
    unsigned lmask = (1u << lane) - 1u;

    int stride = gridDim.x * blockDim.x;
    int wbase  = blockIdx.x * blockDim.x + (threadIdx.x & ~31);

    float acc = 0.0f;
    int cnt = 0;   // warp-uniform survivor count (stack depth, always < 32)

    for (int base = wbase; base < n4; base += stride * 4) {
        // ---- Phase 1: 4 batched stream loads (max LDG MLP) ----
        int i0 = base + lane;
        int i1 = i0 + stride;
        int i2 = i1 + stride;
        int i3 = i2 + stride;
        bool r0 = i0 < n4, r1 = i1 < n4, r2 = i2 < n4, r3 = i3 < n4;
        int4 p0 = make_int4(0,0,0,0), p1 = p0, p2 = p0, p3 = p0;
        if (r0) p0 = __ldcs(&p4[i0]);
        if (r1) p1 = __ldcs(&p4[i1]);
        if (r2) p2 = __ldcs(&p4[i2]);
        if (r3) p3 = __ldcs(&p4[i3]);

        // ---- Phase 2: all 16 LDS gathers + 8 filter evals, no STS between ----
        unsigned short qa0 = s_q[p0.x], qb0 = s_q[p0.y], qc0 = s_q[p0.z], qd0 = s_q[p0.w];
        unsigned short qa1 = s_q[p1.x], qb1 = s_q[p1.y], qc1 = s_q[p1.z], qd1 = s_q[p1.w];
        unsigned short qa2 = s_q[p2.x], qb2 = s_q[p2.y], qc2 = s_q[p2.z], qd2 = s_q[p2.w];
        unsigned short qa3 = s_q[p3.x], qb3 = s_q[p3.y], qc3 = s_q[p3.z], qd3 = s_q[p3.w];

        bool s0a = r0 && swar_pass(expand_q(qa0), expand_q(qb0));
        bool s0b = r0 && swar_pass(expand_q(qc0), expand_q(qd0));
        bool s1a = r1 && swar_pass(expand_q(qa1), expand_q(qb1));
        bool s1b = r1 && swar_pass(expand_q(qc1), expand_q(qd1));
        bool s2a = r2 && swar_pass(expand_q(qa2), expand_q(qb2));
        bool s2b = r2 && swar_pass(expand_q(qc2), expand_q(qd2));
        bool s3a = r3 && swar_pass(expand_q(qa3), expand_q(qb3));
        bool s3b = r3 && swar_pass(expand_q(qc3), expand_q(qd3));

        // ---- Phase 3: compaction (touches only wbuf + rare dense path) ----
        COMPACT_SLOT(s0a, p0.x, p0.y)
        COMPACT_SLOT(s0b, p0.z, p0.w)
        COMPACT_SLOT(s1a, p1.x, p1.y)
        COMPACT_SLOT(s1b, p1.z, p1.w)
        COMPACT_SLOT(s2a, p2.x, p2.y)
        COMPACT_SLOT(s2b, p2.z, p2.w)
        COMPACT_SLOT(s3a, p3.x, p3.y)
        COMPACT_SLOT(s3b, p3.z, p3.w)
    }
    // Drain remaining survivors (< 32).
    __syncwarp();
    if (lane < cnt) {
        uint2 e = wbuf[lane];
        acc += pair_full((int)e.x, (int)e.y, Lx, Ly, Lz, iLx, iLy, iLz);
    }
    // Defensive odd-pair tail (not hit for 16M pairs).
    if (blockIdx.x == 0 && threadIdx.x == 0 && (npairs & 1)) {
        const int* pp = (const int*)p4;
        acc += pair_full(pp[2*(npairs-1)], pp[2*(npairs-1)+1],
                         Lx, Ly, Lz, iLx, iLy, iLz);
    }

    // Deterministic warp + block reduction in double, one atomic per block.
    double dacc = (double)acc;
    #pragma unroll
    for (int o = 16; o > 0; o >>= 1)
        dacc += __shfl_down_sync(0xffffffffu, dacc, o);

    __shared__ double wsum[32];
    __shared__ bool s_last;
    if (lane == 0) wsum[wid] = dacc;
    __syncthreads();
    if (wid == 0) {
        int nw = blockDim.x >> 5;
        double v = (lane < nw) ? wsum[lane] : 0.0;
        #pragma unroll
        for (int o = 16; o > 0; o >>= 1)
            v += __shfl_down_sync(0xffffffffu, v, o);
        if (lane == 0) {
            atomicAdd(&g_accum, v);
            __threadfence();
            unsigned old = atomicAdd(&g_done, 1u);
            s_last = (old == gridDim.x - 1);
        }
    }
    __syncthreads();
    if (s_last && threadIdx.x == 0) {
        out[0] = (float)(*(volatile double*)&g_accum);
    }
}

extern "C" void kernel_launch(void* const* d_in, const int* in_sizes, int n_in,
                              void* d_out, int out_size) {
    const float* coords  = (const float*)d_in[0];
    const float* box     = (const float*)d_in[1];
    const float* charges = (const float*)d_in[2];
    const float* sigma   = (const float*)d_in[3];
    const float* eps     = (const float*)d_in[4];
    const int*   pairs   = (const int*)d_in[5];

    int n      = in_sizes[2];       // N atoms
    int npairs = in_sizes[5] / 2;   // pair count
    int n4     = npairs / 2;        // int4 loads (2 pairs each)

    int tchunks = (n * 2 + 15) / 16;              // 16B chunks for the u16 table
    int smem_bytes = tchunks * 16 + 32 * 64 * 8;  // table + 32 warp stacks
    cudaFuncSetAttribute(pair_kernel,
                         cudaFuncAttributeMaxDynamicSharedMemorySize, smem_bytes);

    int nsm = 148;
    cudaDeviceGetAttribute(&nsm, cudaDevAttrMultiProcessorCount, 0);

    pack_kernel<<<(n + 255) / 256, 256>>>(coords, charges, sigma, eps, n);
    pair_kernel<<<nsm, 1024, smem_bytes>>>((const int4*)pairs, n4, npairs, box,
                                           n, tchunks, (float*)d_out);
}

// round 9
// speedup vs baseline: 1.8543x; 1.1008x over previous
#include <cuda_runtime.h>

#define NMAX 100000
#define CUTOFF2 0.81f
#define PREFAC 138.93544539709032f

// Mixed-radix SWAR filter layout (table value is directly SWAR-ready, no expand):
//   x: 32-cell (5-bit value) in 6-bit field at bits 0-5   (cell 0.3125)
//   y: 32-cell (5-bit value) in 6-bit field at bits 6-11  (cell 0.3125)
//   z: 16-cell (4-bit value) at bits 12-15; its guard overflows into bit 16
//      of the 32-bit register (cell 0.625)
#define SWG   0x10820u   // +fieldsize per field: 32<<0 | 32<<6 | 16<<12 (guard bits 5,11,16)
#define SWM   0x0F7DFu   // value masks: 31 | 31<<6 | 15<<12
#define SWK1  0x020C3u   // +3 | +3<<6 | +2<<12
#define SWK2  0x0B659u   // +25 | +25<<6 | +11<<12

__device__ __align__(16) float4 g_posq[NMAX];
__device__ __align__(8)  float2 g_sigeps[NMAX];
__device__ __align__(16) unsigned short g_qpos[NMAX + 16];
__device__ double g_accum;
__device__ unsigned g_done;

// Fully-coalesced pack: stage xyz through smem so global reads vectorize.
__global__ void __launch_bounds__(256)
pack_kernel(const float* __restrict__ coords,
            const float* __restrict__ charges,
            const float* __restrict__ sigma,
            const float* __restrict__ eps,
            int n) {
    __shared__ float sc[256 * 3];
    int base = blockIdx.x * 256;
    int n3 = n * 3;
    for (int t = threadIdx.x; t < 768; t += 256) {
        int g = base * 3 + t;
        sc[t] = (g < n3) ? coords[g] : 0.0f;
    }
    __syncthreads();
    int a = base + threadIdx.x;
    if (a == 0) { g_accum = 0.0; g_done = 0u; }
    if (a < n) {
        float x = sc[threadIdx.x*3], y = sc[threadIdx.x*3+1], z = sc[threadIdx.x*3+2];
        g_posq[a]   = make_float4(x, y, z, charges[a]);
        g_sigeps[a] = make_float2(sigma[a], eps[a]);
        // Exact cell assignment (double mul avoids boundary misrounding).
        int qx = min(31, max(0, (int)((double)x * 3.2)));
        int qy = min(31, max(0, (int)((double)y * 3.2)));
        int qz = min(15, max(0, (int)((double)z * 1.6)));
        g_qpos[a] = (unsigned short)(qx | (qy << 6) | (qz << 12));
    }
}

// Conservative filter: pass iff min-image cell diff <= 3 in x,y and <= 2 in z.
// Rejects provably have r > 0.9 (x/y: 3*0.3125=0.9375 via |d|>=4 => r>=3 cells;
// z: |d|>=3 => dz >= 2*0.625 = 1.25).
__device__ __forceinline__ bool swar_pass(unsigned a, unsigned b) {
    unsigned d = (a | SWG) - b;        // (fieldsize + ca - cb) per field, no borrows
    unsigned f = (d & SWM) + SWK1;     // (dc mod size) + slack
    unsigned g = (f & SWM) + SWK2;     // guard set iff outside window
    return (g & SWG) == 0u;
}

// Exact energy path (identical math to the reference), run densely on survivors.
__device__ __forceinline__ float pair_full(int i, int j,
                                           float Lx, float Ly, float Lz,
                                           float iLx, float iLy, float iLz) {
    float4 ai = g_posq[i];
    float4 aj = g_posq[j];
    float dx = ai.x - aj.x;
    float dy = ai.y - aj.y;
    float dz = ai.z - aj.z;
    dx -= Lx * rintf(dx * iLx);
    dy -= Ly * rintf(dy * iLy);
    dz -= Lz * rintf(dz * iLz);
    float r2 = dx*dx + dy*dy + dz*dz;
    bool valid = (r2 < CUTOFF2) && ((i / 3) != (j / 3));
    if (!valid) return 0.0f;
    float inv_r = rsqrtf(r2);
    float e = PREFAC * ai.w * aj.w * inv_r;
    float2 si = g_sigeps[i];
    float2 sj = g_sigeps[j];
    float sig = 0.5f * (si.x + sj.x);
    float ep  = sqrtf(si.y * sj.y);
    float sr2 = sig * sig / r2;
    float sr6 = sr2 * sr2 * sr2;
    return e + 4.0f * ep * (sr6 * sr6 - sr6);
}

extern __shared__ unsigned short s_q[];

__global__ void __launch_bounds__(1024, 1)
pair_kernel(const int4* __restrict__ p4, int n4, int npairs,
            const float* __restrict__ box, int tchunks,
            float* __restrict__ out) {
    // Cooperative smem fill of the quantized table (uint4 chunks).
    {
        const uint4* src = (const uint4*)g_qpos;
        uint4* dst = (uint4*)s_q;
        for (int t = threadIdx.x; t < tchunks; t += blockDim.x) dst[t] = src[t];
    }
    // Per-warp 64-entry survivor stacks live after the table.
    uint2* allbuf = (uint2*)(s_q + tchunks * 8);
    __syncthreads();

    const float Lx = box[0], Ly = box[4], Lz = box[8];
    const float iLx = 1.0f / Lx, iLy = 1.0f / Ly, iLz = 1.0f / Lz;

    int lane = threadIdx.x & 31;
    int wid  = threadIdx.x >> 5;
    uint2* wbuf = allbuf + wid * 64;
    unsigned lmask = (1u << lane) - 1u;

    int stride = gridDim.x * blockDim.x;
    int wbase  = blockIdx.x * blockDim.x + (threadIdx.x & ~31);

    float acc = 0.0f;
    int cnt = 0;   // warp-uniform survivor stack depth (always < 32 at loop top)

    for (int base = wbase; base < n4; base += stride * 4) {
        // ---- Phase 1: 4 batched stream loads (max LDG MLP) ----
        int i0 = base + lane;
        int i1 = i0 + stride;
        int i2 = i1 + stride;
        int i3 = i2 + stride;
        bool r0 = i0 < n4, r1 = i1 < n4, r2 = i2 < n4, r3 = i3 < n4;
        int4 p0 = make_int4(0,0,0,0), p1 = p0, p2 = p0, p3 = p0;
        if (r0) p0 = __ldcs(&p4[i0]);
        if (r1) p1 = __ldcs(&p4[i1]);
        if (r2) p2 = __ldcs(&p4[i2]);
        if (r3) p3 = __ldcs(&p4[i3]);

        // ---- Phase 2: all 16 LDS gathers + 8 filter evals (no expand, no STS) ----
        unsigned qa0 = s_q[p0.x], qb0 = s_q[p0.y], qc0 = s_q[p0.z], qd0 = s_q[p0.w];
        unsigned qa1 = s_q[p1.x], qb1 = s_q[p1.y], qc1 = s_q[p1.z], qd1 = s_q[p1.w];
        unsigned qa2 = s_q[p2.x], qb2 = s_q[p2.y], qc2 = s_q[p2.z], qd2 = s_q[p2.w];
        unsigned qa3 = s_q[p3.x], qb3 = s_q[p3.y], qc3 = s_q[p3.z], qd3 = s_q[p3.w];

        bool s0 = r0 && swar_pass(qa0, qb0);
        bool s1 = r0 && swar_pass(qc0, qd0);
        bool s2 = r1 && swar_pass(qa1, qb1);
        bool s3 = r1 && swar_pass(qc1, qd1);
        bool s4 = r2 && swar_pass(qa2, qb2);
        bool s5 = r2 && swar_pass(qc2, qd2);
        bool s6 = r3 && swar_pass(qa3, qb3);
        bool s7 = r3 && swar_pass(qc3, qd3);

        // ---- Phase 3: bit-plane ballot compaction (4 independent ballots) ----
        int c = (int)s0 + s1 + s2 + s3 + s4 + s5 + s6 + s7;   // 0..8
        unsigned b0 = __ballot_sync(0xffffffffu, c & 1);
        unsigned b1 = __ballot_sync(0xffffffffu, c & 2);
        unsigned b2 = __ballot_sync(0xffffffffu, c & 4);
        unsigned b3 = __ballot_sync(0xffffffffu, c & 8);
        int excl  = __popc(b0 & lmask) + 2*__popc(b1 & lmask)
                  + 4*__popc(b2 & lmask) + 8*__popc(b3 & lmask);
        int total = __popc(b0) + 2*__popc(b1) + 4*__popc(b2) + 8*__popc(b3);

        if (cnt + total > 63) {
            // Rare overflow fallback (warp-uniform branch): evaluate directly.
            if (s0) acc += pair_full(p0.x, p0.y, Lx, Ly, Lz, iLx, iLy, iLz);
            if (s1) acc += pair_full(p0.z, p0.w, Lx, Ly, Lz, iLx, iLy, iLz);
            if (s2) acc += pair_full(p1.x, p1.y, Lx, Ly, Lz, iLx, iLy, iLz);
            if (s3) acc += pair_full(p1.z, p1.w, Lx, Ly, Lz, iLx, iLy, iLz);
            if (s4) acc += pair_full(p2.x, p2.y, Lx, Ly, Lz, iLx, iLy, iLz);
            if (s5) acc += pair_full(p2.z, p2.w, Lx, Ly, Lz, iLx, iLy, iLz);
            if (s6) acc += pair_full(p3.x, p3.y, Lx, Ly, Lz, iLx, iLy, iLz);
            if (s7) acc += pair_full(p3.z, p3.w, Lx, Ly, Lz, iLx, iLy, iLz);
        } else {
            int pos = cnt + excl;
            if (s0) wbuf[pos] = make_uint2((unsigned)p0.x, (unsigned)p0.y); pos += s0;
            if (s1) wbuf[pos] = make_uint2((unsigned)p0.z, (unsigned)p0.w); pos += s1;
            if (s2) wbuf[pos] = make_uint2((unsigned)p1.x, (unsigned)p1.y); pos += s2;
            if (s3) wbuf[pos] = make_uint2((unsigned)p1.z, (unsigned)p1.w); pos += s3;
            if (s4) wbuf[pos] = make_uint2((unsigned)p2.x, (unsigned)p2.y); pos += s4;
            if (s5) wbuf[pos] = make_uint2((unsigned)p2.z, (unsigned)p2.w); pos += s5;
            if (s6) wbuf[pos] = make_uint2((unsigned)p3.x, (unsigned)p3.y); pos += s6;
            if (s7) wbuf[pos] = make_uint2((unsigned)p3.z, (unsigned)p3.w);
            cnt += total;
            if (cnt >= 32) {
                cnt -= 32;
                __syncwarp();
                uint2 e = wbuf[cnt + lane];
                acc += pair_full((int)e.x, (int)e.y, Lx, Ly, Lz, iLx, iLy, iLz);
                __syncwarp();   // WAR: next iter's pushes reuse the read slots
            }
        }
    }
    // Drain remaining survivors (< 32).
    __syncwarp();
    if (lane < cnt) {
        uint2 e = wbuf[lane];
        acc += pair_full((int)e.x, (int)e.y, Lx, Ly, Lz, iLx, iLy, iLz);
    }
    // Defensive odd-pair tail (not hit for 16M pairs).
    if (blockIdx.x == 0 && threadIdx.x == 0 && (npairs & 1)) {
        const int* pp = (const int*)p4;
        acc += pair_full(pp[2*(npairs-1)], pp[2*(npairs-1)+1],
                         Lx, Ly, Lz, iLx, iLy, iLz);
    }

    // Deterministic warp + block reduction in double, one atomic per block.
    double dacc = (double)acc;
    #pragma unroll
    for (int o = 16; o > 0; o >>= 1)
        dacc += __shfl_down_sync(0xffffffffu, dacc, o);

    __shared__ double wsum[32];
    __shared__ bool s_last;
    if (lane == 0) wsum[wid] = dacc;
    __syncthreads();
    if (wid == 0) {
        int nw = blockDim.x >> 5;
        double v = (lane < nw) ? wsum[lane] : 0.0;
        #pragma unroll
        for (int o = 16; o > 0; o >>= 1)
            v += __shfl_down_sync(0xffffffffu, v, o);
        if (lane == 0) {
            atomicAdd(&g_accum, v);
            __threadfence();
            unsigned old = atomicAdd(&g_done, 1u);
            s_last = (old == gridDim.x - 1);
        }
    }
    __syncthreads();
    if (s_last && threadIdx.x == 0) {
        out[0] = (float)(*(volatile double*)&g_accum);
    }
}

extern "C" void kernel_launch(void* const* d_in, const int* in_sizes, int n_in,
                              void* d_out, int out_size) {
    const float* coords  = (const float*)d_in[0];
    const float* box     = (const float*)d_in[1];
    const float* charges = (const float*)d_in[2];
    const float* sigma   = (const float*)d_in[3];
    const float* eps     = (const float*)d_in[4];
    const int*   pairs   = (const int*)d_in[5];

    int n      = in_sizes[2];       // N atoms
    int npairs = in_sizes[5] / 2;   // pair count
    int n4     = npairs / 2;        // int4 loads (2 pairs each)

    int tchunks = (n * 2 + 15) / 16;              // 16B chunks for the u16 table
    int smem_bytes = tchunks * 16 + 32 * 64 * 8;  // table + 32 warp stacks
    cudaFuncSetAttribute(pair_kernel,
                         cudaFuncAttributeMaxDynamicSharedMemorySize, smem_bytes);

    int nsm = 148;
    cudaDeviceGetAttribute(&nsm, cudaDevAttrMultiProcessorCount, 0);

    pack_kernel<<<(n + 255) / 256, 256>>>(coords, charges, sigma, eps, n);
    pair_kernel<<<nsm, 1024, smem_bytes>>>((const int4*)pairs, n4, npairs, box,
                                           tchunks, (float*)d_out);
}